// round 11
// baseline (speedup 1.0000x reference)
#include <cuda_runtime.h>
#include <cuda_bf16.h>
#include <cstdint>

// Problem constants
#define BATCH 64
#define NWIN  256
#define HDIM  768
#define C_AB   (0.1f / 768.0f)   // ALPHA*BETA
#define C_EM   0.9f              // 1 - BETA
#define C_K1   0.1f
#define C_BP   1.2f
#define C_AVDL 50.0f

// etdf accumulator (each (b,q) written exactly once per launch)
__device__ float g_etdf[BATCH * NWIN];
// per-batch CTA arrival counter (zero-init; winner resets to 0 each launch)
__device__ int   g_cnt[BATCH];

// ---------------- SMEM layout ----------------
// Tiles use 80-byte row stride (64B data + 16B pad) -> conflict-free ldmatrix.
// Stage layout: Ah@0 (10240), Bh@10240 (20480), Al@30720, Bl@40960.
// lo tile = hi tile + LO_DLT for both A and B.
#define TSTRIDE 80
#define AH_OFF  0
#define BH_OFF  10240
#define LO_DLT  30720
#define STAGE_BYTES 61440
#define TBL_OFF (2 * STAGE_BYTES)            // 122880
//   dm f[256] @ +0, tab f[256] @ +1024, tem f[256] @ +2048, dc i[256] @ +3072,
//   qm f[128] @ +4096, qc i[128] @ +4608
#define RED_OFF (TBL_OFF + 5120)             // 128000: red[512] floats
#define SMEM_TOTAL (RED_OFF + 2048)          // 130048 bytes

#define N_CHUNK 24      // 768 / 32
#define KCH     32      // K elements per chunk

static __device__ __forceinline__ uint32_t smem_u32(const void* p) {
    uint32_t a;
    asm("{ .reg .u64 t; cvta.to.shared.u64 t, %1; cvt.u32.u64 %0, t; }"
        : "=r"(a) : "l"(p));
    return a;
}

#define LDMX4(R, addr)                                                        \
    asm volatile("ldmatrix.sync.aligned.m8n8.x4.shared.b16 {%0,%1,%2,%3}, [%4];" \
                 : "=r"((R)[0]), "=r"((R)[1]), "=r"((R)[2]), "=r"((R)[3])     \
                 : "r"(addr))

#define MMA_BF16(D, A, B0, B1)                                                \
    asm volatile("mma.sync.aligned.m16n8k16.row.col.f32.bf16.bf16.f32 "       \
                 "{%0,%1,%2,%3}, {%4,%5,%6,%7}, {%8,%9}, {%0,%1,%2,%3};"      \
                 : "+f"((D)[0]), "+f"((D)[1]), "+f"((D)[2]), "+f"((D)[3])     \
                 : "r"((A)[0]), "r"((A)[1]), "r"((A)[2]), "r"((A)[3]),        \
                   "r"(B0), "r"(B1))

// ---------------------------------------------------------------------------
// Fused kernel: per-CTA 128x256 tile of one batch, hi/lo bf16 split GEMM via
// mma.sync (3 passes: ah*bh + al*bh + ah*bl), fused epilogue + fused BM25
// score (computed by the second-arriving CTA of each batch).
// 512 threads: warp (mi,ni) = (wid>>2, wid&3), warp tile 32x64.
// ---------------------------------------------------------------------------
__global__ void __launch_bounds__(512, 1) fused_kernel(
    const float* __restrict__ qrep, const float* __restrict__ drep,
    const float* __restrict__ qtw,
    const int4* __restrict__ qids, const int4* __restrict__ dids,
    const int* __restrict__ dtfs,
    float* __restrict__ outmat, float* __restrict__ sout) {

    extern __shared__ char smem[];
    const uint32_t sb = smem_u32(smem);

    const int tid  = threadIdx.x;
    const int lane = tid & 31;
    const int wid  = tid >> 5;
    const int mi   = wid >> 2;   // 0..3, warp M position (32 rows)
    const int ni   = wid & 3;    // 0..3, warp N position (64 cols)

    const int b     = blockIdx.x >> 1;
    const int tmrow = (blockIdx.x & 1) * 128;

    // ---- epilogue tables (written before first sync, read after mainloop) ----
    {
        float* dm_s  = (float*)(smem + TBL_OFF);
        float* tab_s = (float*)(smem + TBL_OFF + 1024);
        float* tem_s = (float*)(smem + TBL_OFF + 2048);
        int*   dc_s  = (int*)  (smem + TBL_OFF + 3072);
        float* qm_s  = (float*)(smem + TBL_OFF + 4096);
        int*   qc_s  = (int*)  (smem + TBL_OFF + 4608);
        if (tid < 256) {
            int4 di = dids[b * NWIN + tid];
            dm_s[tid] = (di.x | di.y | di.z | di.w) ? 1.0f : 0.0f;
            dc_s[tid] = di.x | (di.y << 8) | (di.z << 16) | (di.w << 24);
            float tf  = (float)dtfs[b * NWIN + tid];
            tab_s[tid] = tf * C_AB;
            tem_s[tid] = tf * C_EM;
        } else if (tid < 384) {
            int t = tid - 256;
            int4 qi = qids[b * NWIN + tmrow + t];
            qm_s[t] = (qi.x | qi.y | qi.z | qi.w) ? 1.0f : 0.0f;
            qc_s[t] = qi.x | (qi.y << 8) | (qi.z << 16) | (qi.w << 24);
        }
    }

    const float* Aep = qrep + (size_t)(b * NWIN + tmrow) * HDIM;
    const float* Bep = drep + (size_t)(b * NWIN) * HDIM;

    float acc[2][8][4];
#pragma unroll
    for (int mt = 0; mt < 2; mt++)
#pragma unroll
        for (int nt = 0; nt < 8; nt++)
#pragma unroll
            for (int e = 0; e < 4; e++) acc[mt][nt][e] = 0.0f;

    // 3072 float4 tasks/chunk (A rows: 1024, B rows: 2048), 6 per thread.
    // Walking pointers (advance 8 float4 = 32 floats per chunk) + smem hi
    // offsets (lo = hi + LO_DLT).
    const float4* tptr[6];
    uint32_t toff[6];
#pragma unroll
    for (int i = 0; i < 6; i++) {
        int t = tid + i * 512;
        int row, kq;
        if (t < 1024) {
            row = t >> 3; kq = t & 7;
            tptr[i] = (const float4*)(Aep + (size_t)row * HDIM) + kq;
            toff[i] = AH_OFF + (uint32_t)(row * TSTRIDE + kq * 8);
        } else {
            int u = t - 1024;
            row = u >> 3; kq = u & 7;
            tptr[i] = (const float4*)(Bep + (size_t)row * HDIM) + kq;
            toff[i] = BH_OFF + (uint32_t)(row * TSTRIDE + kq * 8);
        }
    }

    float4 pf[3];

    // convert one float4 -> hi/lo bf16 pairs, store to stage
    auto cvt_store = [&](int i, float4 f, char* stg) {
        __nv_bfloat162 h01 = __floats2bfloat162_rn(f.x, f.y);
        __nv_bfloat162 h23 = __floats2bfloat162_rn(f.z, f.w);
        __nv_bfloat162 l01 = __floats2bfloat162_rn(f.x - __bfloat162float(h01.x),
                                                   f.y - __bfloat162float(h01.y));
        __nv_bfloat162 l23 = __floats2bfloat162_rn(f.z - __bfloat162float(h23.x),
                                                   f.w - __bfloat162float(h23.y));
        union { __nv_bfloat162 h[2]; uint2 u; } H, L;
        H.h[0] = h01; H.h[1] = h23; L.h[0] = l01; L.h[1] = l23;
        char* hp = stg + toff[i];
        *(uint2*)hp = H.u;
        *(uint2*)(hp + LO_DLT) = L.u;
    };

    // ldmatrix lane address components (80B stride rows)
    const int arow  = ((lane >> 3) & 1) * 8 + (lane & 7);
    const int akoff = (lane >> 4) * 16;
    const int brow  = ((lane >> 4) & 1) * 8 + (lane & 7);
    const int bkoff = ((lane >> 3) & 1) * 16;
    const uint32_t aLane = (uint32_t)((mi * 32 + arow) * TSTRIDE + akoff);
    const uint32_t bLane = BH_OFF + (uint32_t)((ni * 64 + brow) * TSTRIDE + bkoff);

    // ---- prologue: fill stage 0 with chunk 0 ----
    {
        char* stg0 = smem;
#pragma unroll
        for (int i = 0; i < 3; i++) pf[i] = *tptr[i];
#pragma unroll
        for (int i = 0; i < 3; i++) cvt_store(i, pf[i], stg0);
#pragma unroll
        for (int i = 3; i < 6; i++) pf[i - 3] = *tptr[i];
#pragma unroll
        for (int i = 3; i < 6; i++) cvt_store(i, pf[i - 3], stg0);
#pragma unroll
        for (int i = 0; i < 6; i++) tptr[i] += 8;
    }
    __syncthreads();

    // ---- mainloop ----
    for (int c = 0; c < N_CHUNK; c++) {
        const int s = c & 1;
        const bool more = (c + 1 < N_CHUNK);
        const uint32_t stg = sb + s * STAGE_BYTES;
        char* nstg = smem + (s ^ 1) * STAGE_BYTES;

        if (more) {
#pragma unroll
            for (int i = 0; i < 3; i++) pf[i] = *tptr[i];
        }

        // ks = 0 MMAs
        {
            uint32_t ah[2][4], al[2][4];
            const uint32_t aAddr = stg + aLane;
            LDMX4(ah[0], aAddr);
            LDMX4(ah[1], aAddr + 16 * TSTRIDE);
            LDMX4(al[0], aAddr + LO_DLT);
            LDMX4(al[1], aAddr + LO_DLT + 16 * TSTRIDE);
#pragma unroll
            for (int ntp = 0; ntp < 4; ntp++) {
                const uint32_t bAddr = stg + bLane + ntp * 16 * TSTRIDE;
                uint32_t bh[4], bl[4];
                LDMX4(bh, bAddr);
                LDMX4(bl, bAddr + LO_DLT);
                MMA_BF16(acc[0][2 * ntp],     ah[0], bh[0], bh[1]);
                MMA_BF16(acc[0][2 * ntp + 1], ah[0], bh[2], bh[3]);
                MMA_BF16(acc[1][2 * ntp],     ah[1], bh[0], bh[1]);
                MMA_BF16(acc[1][2 * ntp + 1], ah[1], bh[2], bh[3]);
                MMA_BF16(acc[0][2 * ntp],     al[0], bh[0], bh[1]);
                MMA_BF16(acc[0][2 * ntp + 1], al[0], bh[2], bh[3]);
                MMA_BF16(acc[1][2 * ntp],     al[1], bh[0], bh[1]);
                MMA_BF16(acc[1][2 * ntp + 1], al[1], bh[2], bh[3]);
                MMA_BF16(acc[0][2 * ntp],     ah[0], bl[0], bl[1]);
                MMA_BF16(acc[0][2 * ntp + 1], ah[0], bl[2], bl[3]);
                MMA_BF16(acc[1][2 * ntp],     ah[1], bl[0], bl[1]);
                MMA_BF16(acc[1][2 * ntp + 1], ah[1], bl[2], bl[3]);
            }
        }

        if (more) {
#pragma unroll
            for (int i = 0; i < 3; i++) cvt_store(i, pf[i], nstg);
#pragma unroll
            for (int i = 3; i < 6; i++) pf[i - 3] = *tptr[i];
        }

        // ks = 1 MMAs
        {
            uint32_t ah[2][4], al[2][4];
            const uint32_t aAddr = stg + aLane + 32;
            LDMX4(ah[0], aAddr);
            LDMX4(ah[1], aAddr + 16 * TSTRIDE);
            LDMX4(al[0], aAddr + LO_DLT);
            LDMX4(al[1], aAddr + LO_DLT + 16 * TSTRIDE);
#pragma unroll
            for (int ntp = 0; ntp < 4; ntp++) {
                const uint32_t bAddr = stg + bLane + ntp * 16 * TSTRIDE + 32;
                uint32_t bh[4], bl[4];
                LDMX4(bh, bAddr);
                LDMX4(bl, bAddr + LO_DLT);
                MMA_BF16(acc[0][2 * ntp],     ah[0], bh[0], bh[1]);
                MMA_BF16(acc[0][2 * ntp + 1], ah[0], bh[2], bh[3]);
                MMA_BF16(acc[1][2 * ntp],     ah[1], bh[0], bh[1]);
                MMA_BF16(acc[1][2 * ntp + 1], ah[1], bh[2], bh[3]);
                MMA_BF16(acc[0][2 * ntp],     al[0], bh[0], bh[1]);
                MMA_BF16(acc[0][2 * ntp + 1], al[0], bh[2], bh[3]);
                MMA_BF16(acc[1][2 * ntp],     al[1], bh[0], bh[1]);
                MMA_BF16(acc[1][2 * ntp + 1], al[1], bh[2], bh[3]);
                MMA_BF16(acc[0][2 * ntp],     ah[0], bl[0], bl[1]);
                MMA_BF16(acc[0][2 * ntp + 1], ah[0], bl[2], bl[3]);
                MMA_BF16(acc[1][2 * ntp],     ah[1], bl[0], bl[1]);
                MMA_BF16(acc[1][2 * ntp + 1], ah[1], bl[2], bl[3]);
            }
        }

        if (more) {
#pragma unroll
            for (int i = 3; i < 6; i++) cvt_store(i, pf[i - 3], nstg);
#pragma unroll
            for (int i = 0; i < 6; i++) tptr[i] += 8;
        }
        __syncthreads();
    }

    // ---------------- epilogue ----------------
    const float* dm_s  = (const float*)(smem + TBL_OFF);
    const float* tab_s = (const float*)(smem + TBL_OFF + 1024);
    const float* tem_s = (const float*)(smem + TBL_OFF + 2048);
    const int*   dc_s  = (const int*)  (smem + TBL_OFF + 3072);
    const float* qm_s  = (const float*)(smem + TBL_OFF + 4096);
    const int*   qc_s  = (const int*)  (smem + TBL_OFF + 4608);

    const int r4 = lane >> 2;
    const int c2 = (lane & 3) * 2;
    float psum[4];

#pragma unroll
    for (int mt = 0; mt < 2; mt++) {
#pragma unroll
        for (int rh = 0; rh < 2; rh++) {
            const int rl = mi * 32 + mt * 16 + rh * 8 + r4;
            const float qm = qm_s[rl];
            const int   qc = qc_s[rl];
            float* orow = outmat + (size_t)(b * NWIN + tmrow + rl) * NWIN;
            float ps = 0.0f;
#pragma unroll
            for (int nt = 0; nt < 8; nt++) {
                const int col = ni * 64 + nt * 8 + c2;
                float v0 = acc[mt][nt][rh * 2 + 0] * qm * dm_s[col];
                float v1 = acc[mt][nt][rh * 2 + 1] * qm * dm_s[col + 1];
                ps += v0 * tab_s[col] + v1 * tab_s[col + 1];
                if (qc == dc_s[col])     ps += tem_s[col];
                if (qc == dc_s[col + 1]) ps += tem_s[col + 1];
                *(float2*)(orow + col) = make_float2(v0, v1);
            }
            psum[mt * 2 + rh] = ps;
        }
    }

#pragma unroll
    for (int p = 0; p < 4; p++) {
        psum[p] += __shfl_xor_sync(0xffffffffu, psum[p], 1);
        psum[p] += __shfl_xor_sync(0xffffffffu, psum[p], 2);
    }
    float* red = (float*)(smem + RED_OFF);   // [4 ni][128 rows]
    if ((lane & 3) == 0) {
#pragma unroll
        for (int mt = 0; mt < 2; mt++)
#pragma unroll
            for (int rh = 0; rh < 2; rh++)
                red[ni * 128 + mi * 32 + mt * 16 + rh * 8 + r4] = psum[mt * 2 + rh];
    }
    __syncthreads();
    if (tid < 128) {
        float e = red[tid] + red[128 + tid] + red[256 + tid] + red[384 + tid];
        g_etdf[b * NWIN + tmrow + tid] = e;
        __threadfence();   // push etdf to GPU scope before the arrival atomic
    }
    __syncthreads();

    // ---------------- fused BM25 score (second-arriving CTA of batch b) ----
    if (tid == 0) {
        int prev = atomicAdd(&g_cnt[b], 1);
        *(int*)smem = (prev == 1) ? 1 : 0;
    }
    __syncthreads();
    const bool win = (*(int*)smem != 0);

    float tfv = 0.0f;
    if (win && tid < 256) tfv = (float)dtfs[b * NWIN + tid];
    red = (float*)(smem + RED_OFF);   // reuse as red[512]
    red[tid] = tfv;
    __syncthreads();
#pragma unroll
    for (int off = 256; off; off >>= 1) {
        if (tid < off) red[tid] += red[tid + off];
        __syncthreads();
    }
    const float dl = red[0];
    __syncthreads();

    float vv = 0.0f;
    if (win && tid < 256) {
        float e   = g_etdf[b * NWIN + tid];
        float nom = e + C_K1 * (1.0f - C_BP + C_BP * dl / C_AVDL);
        vv = qtw[b * NWIN + tid] * (e * (1.0f + C_K1)) / (nom + 1e-8f);
    }
    red[tid] = vv;
    __syncthreads();
#pragma unroll
    for (int off = 256; off; off >>= 1) {
        if (tid < off) red[tid] += red[tid + off];
        __syncthreads();
    }
    if (win && tid == 0) {
        sout[b]  = red[0];
        g_cnt[b] = 0;    // reset for next launch / graph replay
    }
}

// ---------------------------------------------------------------------------
extern "C" void kernel_launch(void* const* d_in, const int* in_sizes, int n_in,
                              void* d_out, int out_size) {
    const float* qrep = (const float*)d_in[0];  // [B, NW, H]
    const float* drep = (const float*)d_in[1];  // [B, NW, H]
    const float* qtw  = (const float*)d_in[2];  // [B, NW]
    const int4*  qids = (const int4*)d_in[3];   // [B, NW, 4]
    const int4*  dids = (const int4*)d_in[4];   // [B, NW, 4]
    const int*   dtfs = (const int*)d_in[5];    // [B, NW]

    float* out  = (float*)d_out;
    float* sout = out;            // s: [B]
    float* mat  = out + BATCH;    // d_expanded_tf: [B, NW, NW]

    static int configured = 0;
    if (!configured) {
        cudaFuncSetAttribute(fused_kernel,
                             cudaFuncAttributeMaxDynamicSharedMemorySize,
                             SMEM_TOTAL);
        configured = 1;
    }

    fused_kernel<<<BATCH * 2, 512, SMEM_TOTAL>>>(qrep, drep, qtw, qids, dids,
                                                 dtfs, mat, sout);
}